// round 5
// baseline (speedup 1.0000x reference)
#include <cuda_runtime.h>

// Problem constants (fixed by the reference)
#define NN 1000000
#define NE 16000000LL

// Scratch (device globals — no allocation allowed)
__device__ float  g_deg[NN];
__device__ float  g_dinv[NN];
__device__ float4 g_g1[NN];     // (x@W1)*dinv per node
__device__ float4 g_acc1[NN];   // conv1 accumulator
__device__ float2 g_g2[NN];     // (relu(h)@W2)*dinv per node
__device__ int    g_is64;       // edge_index dtype flag

__device__ __forceinline__ long long load_idx(const void* p, long long i, int is64) {
    if (is64) return ((const long long*)p)[i];
    return (long long)((const int*)p)[i];
}

// K0: init deg (=1 for self loop), zero acc1, detect index dtype
__global__ __launch_bounds__(256) void k_init(const void* eptr) {
    long long v = (long long)blockIdx.x * blockDim.x + threadIdx.x;
    if (v == 0) {
        // int64 data (values < 2^20, nonneg) has zero high words at odd int32 slots.
        const int* w = (const int*)eptr;
        int any = 0;
        #pragma unroll 4
        for (int i = 0; i < 128; i++) any |= w[2 * i + 1];
        g_is64 = (any == 0) ? 1 : 0;
    }
    if (v < NN) {
        g_deg[v]  = 1.0f;  // self-loop contribution
        g_acc1[v] = make_float4(0.f, 0.f, 0.f, 0.f);
    }
}

// K1: degree scatter over edges (dst half of edge_index)
__global__ __launch_bounds__(256) void k_deg(const void* eptr) {
    long long e = (long long)blockIdx.x * blockDim.x + threadIdx.x;
    if (e >= NE) return;
    int is64 = g_is64;
    long long d = load_idx(eptr, NE + e, is64);
    atomicAdd(&g_deg[d], 1.0f);
}

// K2: dinv = rsqrt(deg); g1 = (x @ W1) * dinv; zero d_out
__global__ __launch_bounds__(256) void k_node1(const float* __restrict__ x,
                                               const float* __restrict__ W1,
                                               float* __restrict__ out) {
    long long v = (long long)blockIdx.x * blockDim.x + threadIdx.x;
    if (v >= NN) return;
    float di = rsqrtf(g_deg[v]);   // deg >= 1 always
    g_dinv[v] = di;
    float2 xv = ((const float2*)x)[v];
    // W1 is [2,4] row-major: h_j = x0*W1[j] + x1*W1[4+j]
    float h0 = fmaf(xv.x, W1[0], xv.y * W1[4]);
    float h1 = fmaf(xv.x, W1[1], xv.y * W1[5]);
    float h2 = fmaf(xv.x, W1[2], xv.y * W1[6]);
    float h3 = fmaf(xv.x, W1[3], xv.y * W1[7]);
    g_g1[v] = make_float4(h0 * di, h1 * di, h2 * di, h3 * di);
    ((float2*)out)[v] = make_float2(0.f, 0.f);
}

// K3: conv1 scatter: acc1[dst] += g1[src]
__global__ __launch_bounds__(256) void k_edge1(const void* eptr) {
    long long e = (long long)blockIdx.x * blockDim.x + threadIdx.x;
    if (e >= NE) return;
    int is64 = g_is64;
    long long s = load_idx(eptr, e, is64);
    long long d = load_idx(eptr, NE + e, is64);
    float4 g = g_g1[s];
    float* a = (float*)g_acc1 + 4 * d;
    atomicAdd(a + 0, g.x);
    atomicAdd(a + 1, g.y);
    atomicAdd(a + 2, g.z);
    atomicAdd(a + 3, g.w);
}

// K4: h = relu(dinv*(acc1 + g1) + b1); g2 = (h @ W2) * dinv
__global__ __launch_bounds__(256) void k_node2(const float* __restrict__ b1,
                                               const float* __restrict__ W2) {
    long long v = (long long)blockIdx.x * blockDim.x + threadIdx.x;
    if (v >= NN) return;
    float di = g_dinv[v];
    float4 a = g_acc1[v];
    float4 g = g_g1[v];
    float t0 = fmaxf(fmaf(di, a.x + g.x, b1[0]), 0.f);
    float t1 = fmaxf(fmaf(di, a.y + g.y, b1[1]), 0.f);
    float t2 = fmaxf(fmaf(di, a.z + g.z, b1[2]), 0.f);
    float t3 = fmaxf(fmaf(di, a.w + g.w, b1[3]), 0.f);
    // W2 is [4,2] row-major: u_j = sum_i t_i * W2[2*i + j]
    float u0 = fmaf(t0, W2[0], fmaf(t1, W2[2], fmaf(t2, W2[4], t3 * W2[6])));
    float u1 = fmaf(t0, W2[1], fmaf(t1, W2[3], fmaf(t2, W2[5], t3 * W2[7])));
    g_g2[v] = make_float2(u0 * di, u1 * di);
}

// K5: conv2 scatter: out[dst] += g2[src]  (accumulate directly in d_out)
__global__ __launch_bounds__(256) void k_edge2(const void* eptr, float* __restrict__ out) {
    long long e = (long long)blockIdx.x * blockDim.x + threadIdx.x;
    if (e >= NE) return;
    int is64 = g_is64;
    long long s = load_idx(eptr, e, is64);
    long long d = load_idx(eptr, NE + e, is64);
    float2 g = g_g2[s];
    atomicAdd(out + 2 * d + 0, g.x);
    atomicAdd(out + 2 * d + 1, g.y);
}

// K6: out = dinv*(out + g2) + b2
__global__ __launch_bounds__(256) void k_node3(const float* __restrict__ b2,
                                               float* __restrict__ out) {
    long long v = (long long)blockIdx.x * blockDim.x + threadIdx.x;
    if (v >= NN) return;
    float di = g_dinv[v];
    float2 o = ((float2*)out)[v];
    float2 g = g_g2[v];
    ((float2*)out)[v] = make_float2(fmaf(di, o.x + g.x, b2[0]),
                                    fmaf(di, o.y + g.y, b2[1]));
}

extern "C" void kernel_launch(void* const* d_in, const int* in_sizes, int n_in,
                              void* d_out, int out_size) {
    const float* x  = (const float*)d_in[0];
    const void*  ei = d_in[1];
    const float* W1 = (const float*)d_in[2];
    const float* b1 = (const float*)d_in[3];
    const float* W2 = (const float*)d_in[4];
    const float* b2 = (const float*)d_in[5];
    float* out = (float*)d_out;

    const int T = 256;
    const int nodeBlocks = (NN + T - 1) / T;
    const int edgeBlocks = (int)((NE + T - 1) / T);

    k_init <<<nodeBlocks, T>>>(ei);
    k_deg  <<<edgeBlocks, T>>>(ei);
    k_node1<<<nodeBlocks, T>>>(x, W1, out);
    k_edge1<<<edgeBlocks, T>>>(ei);
    k_node2<<<nodeBlocks, T>>>(b1, W2);
    k_edge2<<<edgeBlocks, T>>>(ei, out);
    k_node3<<<nodeBlocks, T>>>(b2, out);
}

// round 7
// speedup vs baseline: 1.6203x; 1.6203x over previous
#include <cuda_runtime.h>

// Problem constants (fixed by the reference)
#define NN 1000000
#define NE 16000000LL

// Scratch (device globals — no allocation allowed)
__device__ float  g_deg[NN];
__device__ float  g_dinv[NN];
__device__ float4 g_g1[NN];     // (x@W1)*dinv per node
__device__ float4 g_acc1[NN];   // conv1 accumulator
__device__ float2 g_g2[NN];     // (relu(h)@W2)*dinv per node
__device__ int    g_is64;       // edge_index dtype flag

__device__ __forceinline__ long long load_idx(const void* p, long long i, int is64) {
    if (is64) return __ldg(&((const long long*)p)[i]);
    return (long long)__ldg(&((const int*)p)[i]);
}

// Vectorized global reductions (PTX ISA 8.1+, sm_90+): ONE LTS atomic op for
// 2/4 floats instead of 2/4 scalar ops. This is the LTS-op-count lever.
__device__ __forceinline__ void red_add_v4(float* addr, float4 v) {
    asm volatile("red.global.add.v4.f32 [%0], {%1,%2,%3,%4};"
                 :: "l"(addr), "f"(v.x), "f"(v.y), "f"(v.z), "f"(v.w) : "memory");
}
__device__ __forceinline__ void red_add_v2(float* addr, float2 v) {
    asm volatile("red.global.add.v2.f32 [%0], {%1,%2};"
                 :: "l"(addr), "f"(v.x), "f"(v.y) : "memory");
}

// K0: init deg (=1 for self loop), zero acc1, detect index dtype
__global__ __launch_bounds__(256) void k_init(const void* eptr) {
    long long v = (long long)blockIdx.x * blockDim.x + threadIdx.x;
    if (v == 0) {
        // int64 data (values < 2^20, nonneg) has zero high words at odd int32 slots.
        const int* w = (const int*)eptr;
        int any = 0;
        #pragma unroll 4
        for (int i = 0; i < 128; i++) any |= w[2 * i + 1];
        g_is64 = (any == 0) ? 1 : 0;
    }
    if (v < NN) {
        g_deg[v]  = 1.0f;  // self-loop contribution
        g_acc1[v] = make_float4(0.f, 0.f, 0.f, 0.f);
    }
}

// K1: degree scatter over edges (dst half of edge_index)
__global__ __launch_bounds__(256) void k_deg(const void* eptr) {
    long long e = (long long)blockIdx.x * blockDim.x + threadIdx.x;
    if (e >= NE) return;
    int is64 = g_is64;
    long long d = load_idx(eptr, NE + e, is64);
    atomicAdd(&g_deg[d], 1.0f);
}

// K2: dinv = rsqrt(deg); g1 = (x @ W1) * dinv; zero d_out
__global__ __launch_bounds__(256) void k_node1(const float* __restrict__ x,
                                               const float* __restrict__ W1,
                                               float* __restrict__ out) {
    long long v = (long long)blockIdx.x * blockDim.x + threadIdx.x;
    if (v >= NN) return;
    float di = rsqrtf(g_deg[v]);   // deg >= 1 always
    g_dinv[v] = di;
    float2 xv = ((const float2*)x)[v];
    // W1 is [2,4] row-major: h_j = x0*W1[j] + x1*W1[4+j]
    float h0 = fmaf(xv.x, W1[0], xv.y * W1[4]);
    float h1 = fmaf(xv.x, W1[1], xv.y * W1[5]);
    float h2 = fmaf(xv.x, W1[2], xv.y * W1[6]);
    float h3 = fmaf(xv.x, W1[3], xv.y * W1[7]);
    g_g1[v] = make_float4(h0 * di, h1 * di, h2 * di, h3 * di);
    ((float2*)out)[v] = make_float2(0.f, 0.f);
}

// K3: conv1 scatter: acc1[dst] += g1[src]  — ONE v4 red per edge
__global__ __launch_bounds__(256) void k_edge1(const void* eptr) {
    long long e = (long long)blockIdx.x * blockDim.x + threadIdx.x;
    if (e >= NE) return;
    int is64 = g_is64;
    long long s = load_idx(eptr, e, is64);
    long long d = load_idx(eptr, NE + e, is64);
    float4 g = g_g1[s];
    red_add_v4((float*)g_acc1 + 4 * d, g);   // 16B-aligned (float4 array)
}

// K4: h = relu(dinv*(acc1 + g1) + b1); g2 = (h @ W2) * dinv
__global__ __launch_bounds__(256) void k_node2(const float* __restrict__ b1,
                                               const float* __restrict__ W2) {
    long long v = (long long)blockIdx.x * blockDim.x + threadIdx.x;
    if (v >= NN) return;
    float di = g_dinv[v];
    float4 a = g_acc1[v];
    float4 g = g_g1[v];
    float t0 = fmaxf(fmaf(di, a.x + g.x, b1[0]), 0.f);
    float t1 = fmaxf(fmaf(di, a.y + g.y, b1[1]), 0.f);
    float t2 = fmaxf(fmaf(di, a.z + g.z, b1[2]), 0.f);
    float t3 = fmaxf(fmaf(di, a.w + g.w, b1[3]), 0.f);
    // W2 is [4,2] row-major: u_j = sum_i t_i * W2[2*i + j]
    float u0 = fmaf(t0, W2[0], fmaf(t1, W2[2], fmaf(t2, W2[4], t3 * W2[6])));
    float u1 = fmaf(t0, W2[1], fmaf(t1, W2[3], fmaf(t2, W2[5], t3 * W2[7])));
    g_g2[v] = make_float2(u0 * di, u1 * di);
}

// K5: conv2 scatter: out[dst] += g2[src]  — ONE v2 red per edge
__global__ __launch_bounds__(256) void k_edge2(const void* eptr, float* __restrict__ out) {
    long long e = (long long)blockIdx.x * blockDim.x + threadIdx.x;
    if (e >= NE) return;
    int is64 = g_is64;
    long long s = load_idx(eptr, e, is64);
    long long d = load_idx(eptr, NE + e, is64);
    float2 g = g_g2[s];
    red_add_v2(out + 2 * d, g);              // 8B-aligned
}

// K6: out = dinv*(out + g2) + b2
__global__ __launch_bounds__(256) void k_node3(const float* __restrict__ b2,
                                               float* __restrict__ out) {
    long long v = (long long)blockIdx.x * blockDim.x + threadIdx.x;
    if (v >= NN) return;
    float di = g_dinv[v];
    float2 o = ((float2*)out)[v];
    float2 g = g_g2[v];
    ((float2*)out)[v] = make_float2(fmaf(di, o.x + g.x, b2[0]),
                                    fmaf(di, o.y + g.y, b2[1]));
}

extern "C" void kernel_launch(void* const* d_in, const int* in_sizes, int n_in,
                              void* d_out, int out_size) {
    const float* x  = (const float*)d_in[0];
    const void*  ei = d_in[1];
    const float* W1 = (const float*)d_in[2];
    const float* b1 = (const float*)d_in[3];
    const float* W2 = (const float*)d_in[4];
    const float* b2 = (const float*)d_in[5];
    float* out = (float*)d_out;

    const int T = 256;
    const int nodeBlocks = (NN + T - 1) / T;
    const int edgeBlocks = (int)((NE + T - 1) / T);

    k_init <<<nodeBlocks, T>>>(ei);
    k_deg  <<<edgeBlocks, T>>>(ei);
    k_node1<<<nodeBlocks, T>>>(x, W1, out);
    k_edge1<<<edgeBlocks, T>>>(ei);
    k_node2<<<nodeBlocks, T>>>(b1, W2);
    k_edge2<<<edgeBlocks, T>>>(ei, out);
    k_node3<<<nodeBlocks, T>>>(b2, out);
}

// round 11
// speedup vs baseline: 1.7323x; 1.0691x over previous
#include <cuda_runtime.h>

// Problem constants (fixed by the reference)
#define NN 1000000
#define NE 16000000LL
#define EPT 4                      // edges per thread in edge kernels
#define ETHREADS (NE / EPT)        // 4,000,000 threads, stride = ETHREADS

// Scratch (device globals — no allocation allowed)
__device__ float  g_deg[NN];
__device__ float  g_dinv[NN];
__device__ float4 g_g1[NN];     // (x@W1)*dinv per node
__device__ float4 g_acc1[NN];   // conv1 accumulator
__device__ float2 g_g2[NN];     // (relu(h)@W2)*dinv per node
__device__ int    g_is64;       // edge_index dtype flag

// Vectorized global reductions (PTX ISA 8.1+, sm_90+): ONE LTS op for 2/4 floats.
__device__ __forceinline__ void red_add_v4(float* addr, float4 v) {
    asm volatile("red.global.add.v4.f32 [%0], {%1,%2,%3,%4};"
                 :: "l"(addr), "f"(v.x), "f"(v.y), "f"(v.z), "f"(v.w) : "memory");
}
__device__ __forceinline__ void red_add_v2(float* addr, float2 v) {
    asm volatile("red.global.add.v2.f32 [%0], {%1,%2};"
                 :: "l"(addr), "f"(v.x), "f"(v.y) : "memory");
}

// K0: init deg (=1 for self loop), zero acc1, detect index dtype
__global__ __launch_bounds__(256) void k_init(const void* eptr) {
    long long v = (long long)blockIdx.x * blockDim.x + threadIdx.x;
    if (v == 0) {
        // int64 data (values < 2^20, nonneg) has zero high words at odd int32 slots.
        const int* w = (const int*)eptr;
        int any = 0;
        #pragma unroll 4
        for (int i = 0; i < 128; i++) any |= w[2 * i + 1];
        g_is64 = (any == 0) ? 1 : 0;
    }
    if (v < NN) {
        g_deg[v]  = 1.0f;  // self-loop contribution
        g_acc1[v] = make_float4(0.f, 0.f, 0.f, 0.f);
    }
}

// K1: degree scatter — 4 dst/thread, batched index loads for MLP
__global__ __launch_bounds__(256) void k_deg(const void* eptr) {
    long long t = (long long)blockIdx.x * blockDim.x + threadIdx.x;  // < ETHREADS
    long long d[EPT];
    if (g_is64) {
        const long long* p = (const long long*)eptr + NE;
        #pragma unroll
        for (int i = 0; i < EPT; i++) d[i] = __ldg(p + t + i * ETHREADS);
    } else {
        const int* p = (const int*)eptr + NE;
        #pragma unroll
        for (int i = 0; i < EPT; i++) d[i] = __ldg(p + t + i * ETHREADS);
    }
    #pragma unroll
    for (int i = 0; i < EPT; i++) atomicAdd(&g_deg[d[i]], 1.0f);
}

// K2: dinv = rsqrt(deg); g1 = (x @ W1) * dinv; zero d_out
__global__ __launch_bounds__(256) void k_node1(const float* __restrict__ x,
                                               const float* __restrict__ W1,
                                               float* __restrict__ out) {
    long long v = (long long)blockIdx.x * blockDim.x + threadIdx.x;
    if (v >= NN) return;
    float di = rsqrtf(g_deg[v]);   // deg >= 1 always
    g_dinv[v] = di;
    float2 xv = ((const float2*)x)[v];
    // W1 is [2,4] row-major: h_j = x0*W1[j] + x1*W1[4+j]
    float h0 = fmaf(xv.x, W1[0], xv.y * W1[4]);
    float h1 = fmaf(xv.x, W1[1], xv.y * W1[5]);
    float h2 = fmaf(xv.x, W1[2], xv.y * W1[6]);
    float h3 = fmaf(xv.x, W1[3], xv.y * W1[7]);
    g_g1[v] = make_float4(h0 * di, h1 * di, h2 * di, h3 * di);
    ((float2*)out)[v] = make_float2(0.f, 0.f);
}

// K3: conv1 scatter: acc1[dst] += g1[src] — 4 edges/thread, batched loads
__global__ __launch_bounds__(256) void k_edge1(const void* eptr) {
    long long t = (long long)blockIdx.x * blockDim.x + threadIdx.x;
    long long s[EPT], d[EPT];
    if (g_is64) {
        const long long* ps = (const long long*)eptr;
        const long long* pd = ps + NE;
        #pragma unroll
        for (int i = 0; i < EPT; i++) s[i] = __ldg(ps + t + i * ETHREADS);
        #pragma unroll
        for (int i = 0; i < EPT; i++) d[i] = __ldg(pd + t + i * ETHREADS);
    } else {
        const int* ps = (const int*)eptr;
        const int* pd = ps + NE;
        #pragma unroll
        for (int i = 0; i < EPT; i++) s[i] = __ldg(ps + t + i * ETHREADS);
        #pragma unroll
        for (int i = 0; i < EPT; i++) d[i] = __ldg(pd + t + i * ETHREADS);
    }
    float4 g[EPT];
    #pragma unroll
    for (int i = 0; i < EPT; i++) g[i] = g_g1[s[i]];
    #pragma unroll
    for (int i = 0; i < EPT; i++) red_add_v4((float*)g_acc1 + 4 * d[i], g[i]);
}

// K4: h = relu(dinv*(acc1 + g1) + b1); g2 = (h @ W2) * dinv
__global__ __launch_bounds__(256) void k_node2(const float* __restrict__ b1,
                                               const float* __restrict__ W2) {
    long long v = (long long)blockIdx.x * blockDim.x + threadIdx.x;
    if (v >= NN) return;
    float di = g_dinv[v];
    float4 a = g_acc1[v];
    float4 g = g_g1[v];
    float t0 = fmaxf(fmaf(di, a.x + g.x, b1[0]), 0.f);
    float t1 = fmaxf(fmaf(di, a.y + g.y, b1[1]), 0.f);
    float t2 = fmaxf(fmaf(di, a.z + g.z, b1[2]), 0.f);
    float t3 = fmaxf(fmaf(di, a.w + g.w, b1[3]), 0.f);
    // W2 is [4,2] row-major: u_j = sum_i t_i * W2[2*i + j]
    float u0 = fmaf(t0, W2[0], fmaf(t1, W2[2], fmaf(t2, W2[4], t3 * W2[6])));
    float u1 = fmaf(t0, W2[1], fmaf(t1, W2[3], fmaf(t2, W2[5], t3 * W2[7])));
    g_g2[v] = make_float2(u0 * di, u1 * di);
}

// K5: conv2 scatter: out[dst] += g2[src] — 4 edges/thread, batched loads
__global__ __launch_bounds__(256) void k_edge2(const void* eptr, float* __restrict__ out) {
    long long t = (long long)blockIdx.x * blockDim.x + threadIdx.x;
    long long s[EPT], d[EPT];
    if (g_is64) {
        const long long* ps = (const long long*)eptr;
        const long long* pd = ps + NE;
        #pragma unroll
        for (int i = 0; i < EPT; i++) s[i] = __ldg(ps + t + i * ETHREADS);
        #pragma unroll
        for (int i = 0; i < EPT; i++) d[i] = __ldg(pd + t + i * ETHREADS);
    } else {
        const int* ps = (const int*)eptr;
        const int* pd = ps + NE;
        #pragma unroll
        for (int i = 0; i < EPT; i++) s[i] = __ldg(ps + t + i * ETHREADS);
        #pragma unroll
        for (int i = 0; i < EPT; i++) d[i] = __ldg(pd + t + i * ETHREADS);
    }
    float2 g[EPT];
    #pragma unroll
    for (int i = 0; i < EPT; i++) g[i] = g_g2[s[i]];
    #pragma unroll
    for (int i = 0; i < EPT; i++) red_add_v2(out + 2 * d[i], g[i]);
}

// K6: out = dinv*(out + g2) + b2
__global__ __launch_bounds__(256) void k_node3(const float* __restrict__ b2,
                                               float* __restrict__ out) {
    long long v = (long long)blockIdx.x * blockDim.x + threadIdx.x;
    if (v >= NN) return;
    float di = g_dinv[v];
    float2 o = ((float2*)out)[v];
    float2 g = g_g2[v];
    ((float2*)out)[v] = make_float2(fmaf(di, o.x + g.x, b2[0]),
                                    fmaf(di, o.y + g.y, b2[1]));
}

extern "C" void kernel_launch(void* const* d_in, const int* in_sizes, int n_in,
                              void* d_out, int out_size) {
    const float* x  = (const float*)d_in[0];
    const void*  ei = d_in[1];
    const float* W1 = (const float*)d_in[2];
    const float* b1 = (const float*)d_in[3];
    const float* W2 = (const float*)d_in[4];
    const float* b2 = (const float*)d_in[5];
    float* out = (float*)d_out;

    const int T = 256;
    const int nodeBlocks = (NN + T - 1) / T;
    const int edgeBlocks = (int)(ETHREADS / T);   // 15625, exact (16M/4/256)

    k_init <<<nodeBlocks, T>>>(ei);
    k_deg  <<<edgeBlocks, T>>>(ei);
    k_node1<<<nodeBlocks, T>>>(x, W1, out);
    k_edge1<<<edgeBlocks, T>>>(ei);
    k_node2<<<nodeBlocks, T>>>(b1, W2);
    k_edge2<<<edgeBlocks, T>>>(ei, out);
    k_node3<<<nodeBlocks, T>>>(b2, out);
}